// round 15
// baseline (speedup 1.0000x reference)
#include <cuda_runtime.h>
#include <cuda_bf16.h>
#include <cuda_fp16.h>
#include <cstdint>

// Problem constants
#define Bsz 8
#define SEQ 1024
#define HID 512
#define NHEAD 8
#define HDIM 64
#define BH (Bsz*NHEAD)          // 64
#define ROWS (Bsz*SEQ)          // 8192
#define XROWS (ROWS + 3*HID)    // 9728 : X rows then Wq,Wk,Wv rows

// ---------------------------------------------------------------------------
// Global scratch (pre-split operands, all half2-packed in uint32)
// ---------------------------------------------------------------------------
__device__ uint32_t g_xh[XROWS * (HID/2)];      // X/W hi  [row][256]
__device__ uint32_t g_xl[XROWS * (HID/2)];      // X/W lo
__device__ uint32_t g_qh[BH * SEQ * (HDIM/2)];  // Q hi    [bh][s][32]
__device__ uint32_t g_ql[BH * SEQ * (HDIM/2)];
__device__ uint32_t g_kh[BH * SEQ * (HDIM/2)];  // K hi (pre-scaled by 1/8)
__device__ uint32_t g_kl[BH * SEQ * (HDIM/2)];
__device__ float    g_v [BH * SEQ * HDIM];      // V fp32 [bh][s][d]
__device__ uint32_t g_vth[BH * HDIM * (SEQ/2)]; // V^T hi [bh][d][s-pair]
__device__ uint32_t g_vtl[BH * HDIM * (SEQ/2)];

// ---------------------------------------------------------------------------
// MMA + helpers
// ---------------------------------------------------------------------------
__device__ __forceinline__ void mma16816(float c[4],
    uint32_t a0, uint32_t a1, uint32_t a2, uint32_t a3,
    uint32_t b0, uint32_t b1)
{
    asm volatile(
        "mma.sync.aligned.m16n8k16.row.col.f32.f16.f16.f32 "
        "{%0,%1,%2,%3}, {%4,%5,%6,%7}, {%8,%9}, {%0,%1,%2,%3};\n"
        : "+f"(c[0]), "+f"(c[1]), "+f"(c[2]), "+f"(c[3])
        : "r"(a0), "r"(a1), "r"(a2), "r"(a3), "r"(b0), "r"(b1));
}

// ldmatrix x4: 4 8x8 b16 matrices; lane L supplies row addr for matrix L/8.
__device__ __forceinline__ void ldsm_x4(uint32_t& r0, uint32_t& r1,
                                        uint32_t& r2, uint32_t& r3,
                                        uint32_t addr)
{
    asm volatile(
        "ldmatrix.sync.aligned.m8n8.x4.shared.b16 {%0,%1,%2,%3}, [%4];\n"
        : "=r"(r0), "=r"(r1), "=r"(r2), "=r"(r3) : "r"(addr));
}

__device__ __forceinline__ uint32_t pack_half2(__half a, __half b) {
    return (uint32_t)__half_as_ushort(a) | ((uint32_t)__half_as_ushort(b) << 16);
}
__device__ __forceinline__ void split2(float x, float y, uint32_t& hi, uint32_t& lo) {
    __half hx = __float2half_rn(x), hy = __float2half_rn(y);
    __half lx = __float2half_rn(x - __half2float(hx));
    __half ly = __float2half_rn(y - __half2float(hy));
    hi = pack_half2(hx, hy);
    lo = pack_half2(lx, ly);
}

__device__ __forceinline__ void cp16(uint32_t dst_smem, const void* src) {
    asm volatile("cp.async.cg.shared.global [%0], [%1], 16;\n"
                 :: "r"(dst_smem), "l"(src));
}
#define CP_COMMIT() asm volatile("cp.async.commit_group;\n")
#define CP_WAIT(N)  asm volatile("cp.async.wait_group %0;\n" :: "n"(N))

// smem pitch in uint32 (32 data + 4 pad). LDSM: row r -> bank 4r mod 32,
// 8 rows x 16B cover all 32 banks exactly once -> conflict-free.
#define PP 36
#define TSTRIDE (64 * PP)       // 2304 u32 per tile

// ---------------------------------------------------------------------------
// 1) Split X (8192 rows) and W (1536 rows: Wq,Wk,Wv) into hi/lo half2.
// ---------------------------------------------------------------------------
__global__ __launch_bounds__(128) void split_kernel(
    const float* __restrict__ X,
    const float* __restrict__ Wq, const float* __restrict__ Wk,
    const float* __restrict__ Wv)
{
    const int r = blockIdx.x;
    const int tid = threadIdx.x;
    const float* src;
    if (r < ROWS) src = X + (size_t)r * HID;
    else {
        int wr = r - ROWS;
        const float* W = (wr >> 9) == 0 ? Wq : (wr >> 9) == 1 ? Wk : Wv;
        src = W + (size_t)(wr & 511) * HID;
    }
    float4 v4 = *(const float4*)&src[tid * 4];
    uint32_t h0, l0, h1, l1;
    split2(v4.x, v4.y, h0, l0);
    split2(v4.z, v4.w, h1, l1);
    size_t o = (size_t)r * (HID/2) + tid * 2;
    g_xh[o] = h0; g_xh[o + 1] = h1;
    g_xl[o] = l0; g_xl[o + 1] = l1;
}

// ---------------------------------------------------------------------------
// 2) QKV GEMM on pre-split operands. cp.async 2-stage pipeline + ldmatrix.
//    Tile 64x64, BK=64 (32 u32), 128 threads / 4 warps.
//    MMAs round-robin over all 8 accumulators (dep distance 8).
// ---------------------------------------------------------------------------
__device__ __forceinline__ void qkv_issue(
    uint32_t* smu, int st, int sg, int tid, int row0, int wrow0)
{
    const int kb32 = st * 32;           // u32 col offset within 256-wide row
    const uint32_t base = sg * (4 * TSTRIDE);
#pragma unroll
    for (int u = 0; u < 16; u++) {
        int t = u * 128 + tid;
        int arr = t >> 9;
        int rem = t & 511;
        int r = rem >> 3, seg = rem & 7;
        const uint32_t* src;
        if (arr == 0)      src = g_xh + (size_t)(row0 + r) * 256 + kb32 + seg * 4;
        else if (arr == 1) src = g_xl + (size_t)(row0 + r) * 256 + kb32 + seg * 4;
        else if (arr == 2) src = g_xh + (size_t)(wrow0 + r) * 256 + kb32 + seg * 4;
        else               src = g_xl + (size_t)(wrow0 + r) * 256 + kb32 + seg * 4;
        uint32_t dst = (uint32_t)__cvta_generic_to_shared(
            &smu[base + arr * TSTRIDE + r * PP + seg * 4]);
        cp16(dst, src);
    }
    CP_COMMIT();
}

__global__ __launch_bounds__(128, 2) void qkv_kernel(
    const float* __restrict__ bq, const float* __restrict__ bk,
    const float* __restrict__ bv)
{
    extern __shared__ uint32_t smu[];   // 2 stages x 4 tiles x 2304 = 73728 B
    const int ib = blockIdx.x;          // 128 row tiles
    const int jb = blockIdx.y;          // 24 col tiles
    const int jsel = jb >> 3;           // 0=Q 1=K 2=V
    const int h = jb & 7;

    const float* bias = (jsel == 0) ? bq : (jsel == 1) ? bk : bv;

    const int tid = threadIdx.x;
    const int lane = tid & 31;
    const int w = tid >> 5;
    const int g = lane >> 2;
    const int tig = lane & 3;
    const int row0 = ib * 64;
    const int wrow0 = ROWS + jsel * HID + h * 64;

    const uint32_t smaddr = (uint32_t)__cvta_generic_to_shared(smu);
    const int q8 = lane >> 3;          // 0..3: ldmatrix matrix index
    const int rl = lane & 7;           // row within 8x8 matrix
    const uint32_t laneA = ((w * 16 + (q8 & 1) * 8 + rl) * PP + (q8 >> 1) * 4) * 4;
    const uint32_t laneB = (((q8 >> 1) * 8 + rl) * PP + (q8 & 1) * 4) * 4;

    float acc[8][4];
#pragma unroll
    for (int nt = 0; nt < 8; nt++)
#pragma unroll
        for (int j = 0; j < 4; j++) acc[nt][j] = 0.f;

    qkv_issue(smu, 0, 0, tid, row0, wrow0);

    for (int st = 0; st < 8; st++) {
        int p = st & 1;
        if (st < 7) { qkv_issue(smu, st + 1, 1 - p, tid, row0, wrow0); CP_WAIT(1); }
        else CP_WAIT(0);
        __syncthreads();

        const uint32_t Xhi_a = smaddr + p * (4 * TSTRIDE) * 4;
        const uint32_t Xlo_a = Xhi_a + TSTRIDE * 4;
        const uint32_t Whi_a = Xhi_a + 2 * TSTRIDE * 4;
        const uint32_t Wlo_a = Xhi_a + 3 * TSTRIDE * 4;

#pragma unroll
        for (int kc = 0; kc < 4; kc++) {
            // All fragment loads first: LDSM latency amortized over 24 MMAs
            uint32_t ah0, ah1, ah2, ah3, al0, al1, al2, al3;
            ldsm_x4(ah0, ah1, ah2, ah3, Xhi_a + laneA + kc * 32);
            ldsm_x4(al0, al1, al2, al3, Xlo_a + laneA + kc * 32);
            uint32_t bh[4][4], bl[4][4];
#pragma unroll
            for (int ntp = 0; ntp < 4; ntp++) {
                uint32_t boff = laneB + (uint32_t)(ntp * 16 * PP * 4) + kc * 32;
                ldsm_x4(bh[ntp][0], bh[ntp][1], bh[ntp][2], bh[ntp][3], Whi_a + boff);
                ldsm_x4(bl[ntp][0], bl[ntp][1], bl[ntp][2], bl[ntp][3], Wlo_a + boff);
            }
            // Round-robin: all hh terms, then hl, then lh (dep distance 8)
#pragma unroll
            for (int ntp = 0; ntp < 4; ntp++) {
                mma16816(acc[2 * ntp],     ah0, ah1, ah2, ah3, bh[ntp][0], bh[ntp][1]);
                mma16816(acc[2 * ntp + 1], ah0, ah1, ah2, ah3, bh[ntp][2], bh[ntp][3]);
            }
#pragma unroll
            for (int ntp = 0; ntp < 4; ntp++) {
                mma16816(acc[2 * ntp],     ah0, ah1, ah2, ah3, bl[ntp][0], bl[ntp][1]);
                mma16816(acc[2 * ntp + 1], ah0, ah1, ah2, ah3, bl[ntp][2], bl[ntp][3]);
            }
#pragma unroll
            for (int ntp = 0; ntp < 4; ntp++) {
                mma16816(acc[2 * ntp],     al0, al1, al2, al3, bh[ntp][0], bh[ntp][1]);
                mma16816(acc[2 * ntp + 1], al0, al1, al2, al3, bh[ntp][2], bh[ntp][3]);
            }
        }
        __syncthreads();
    }

    // Epilogue
    const int grow0 = row0 + w * 16 + g;
    const int grow1 = grow0 + 8;
    const int b0i = grow0 >> 10, s0 = grow0 & 1023;
    const int b1i = grow1 >> 10, s1 = grow1 & 1023;
    const int bh0 = b0i * NHEAD + h, bh1 = b1i * NHEAD + h;

    if (jsel == 2) {
        size_t base0 = ((size_t)bh0 * SEQ + s0) * HDIM;
        size_t base1 = ((size_t)bh1 * SEQ + s1) * HDIM;
#pragma unroll
        for (int nt = 0; nt < 8; nt++) {
            int d = nt * 8 + 2 * tig;
            float bv0 = bias[h * 64 + d], bv1 = bias[h * 64 + d + 1];
            *(float2*)&g_v[base0 + d] = make_float2(acc[nt][0] + bv0, acc[nt][1] + bv1);
            *(float2*)&g_v[base1 + d] = make_float2(acc[nt][2] + bv0, acc[nt][3] + bv1);
        }
    } else {
        uint32_t* oh = (jsel == 0) ? g_qh : g_kh;
        uint32_t* ol = (jsel == 0) ? g_ql : g_kl;
        float sc = (jsel == 0) ? 1.0f : 0.125f;   // fold 1/sqrt(64) into K (exact)
        size_t base0 = ((size_t)bh0 * SEQ + s0) * 32;
        size_t base1 = ((size_t)bh1 * SEQ + s1) * 32;
#pragma unroll
        for (int nt = 0; nt < 8; nt++) {
            int d = nt * 8 + 2 * tig;
            int uc = nt * 4 + tig;
            float bv0 = bias[h * 64 + d], bv1 = bias[h * 64 + d + 1];
            uint32_t hi, lo;
            split2((acc[nt][0] + bv0) * sc, (acc[nt][1] + bv1) * sc, hi, lo);
            oh[base0 + uc] = hi; ol[base0 + uc] = lo;
            split2((acc[nt][2] + bv0) * sc, (acc[nt][3] + bv1) * sc, hi, lo);
            oh[base1 + uc] = hi; ol[base1 + uc] = lo;
        }
    }
}

// ---------------------------------------------------------------------------
// 3) Transpose + split V:  g_v [bh][s][d] -> g_vth/g_vtl [bh][d][s-pair]
// ---------------------------------------------------------------------------
__global__ __launch_bounds__(256) void vtrans_kernel()
{
    __shared__ float Vs[64][65];
    const int stile = blockIdx.x;       // 0..15
    const int bh = blockIdx.y;          // 0..63
    const int tid = threadIdx.x;

#pragma unroll
    for (int u = 0; u < 4; u++) {
        int e = u * 256 + tid;
        int r = e >> 4, c4 = (e & 15) * 4;
        float4 v4 = *(const float4*)&g_v[((size_t)bh * SEQ + stile * 64 + r) * HDIM + c4];
        Vs[r][c4 + 0] = v4.x; Vs[r][c4 + 1] = v4.y;
        Vs[r][c4 + 2] = v4.z; Vs[r][c4 + 3] = v4.w;
    }
    __syncthreads();

    const int d = tid >> 2;
    const int q = tid & 3;
    size_t obase = ((size_t)bh * HDIM + d) * (SEQ/2) + stile * 32;
#pragma unroll
    for (int i = 0; i < 8; i++) {
        int sp = q * 8 + i;
        uint32_t hi, lo;
        split2(Vs[2 * sp][d], Vs[2 * sp + 1][d], hi, lo);
        g_vth[obase + sp] = hi;
        g_vtl[obase + sp] = lo;
    }
}

// ---------------------------------------------------------------------------
// 4) Flash attention: 64-row q-tile, 128 threads / 4 warps, 2-stage
//    cp.async pipeline, ldmatrix loads, round-robin MMA scheduling.
//    Stage layout (u32): Khi@0 Klo@2304 Vh@4608 Vl@6912 Ms@9216(+64)
// ---------------------------------------------------------------------------
#define ASTG 9280

__device__ __forceinline__ void attn_issue(
    uint32_t* smu, int kt, int sg, int tid,
    const uint32_t* khp, const uint32_t* klp,
    const uint32_t* vhp, const uint32_t* vlp, const float* mp)
{
    const uint32_t base = sg * ASTG;
#pragma unroll
    for (int u = 0; u < 16; u++) {
        int t = u * 128 + tid;
        int arr = t >> 9;
        int rem = t & 511;
        int r = rem >> 3, seg = rem & 7;
        const uint32_t* src;
        if (arr == 0)      src = khp + (size_t)(kt * 64 + r) * 32 + seg * 4;
        else if (arr == 1) src = klp + (size_t)(kt * 64 + r) * 32 + seg * 4;
        else if (arr == 2) src = vhp + (size_t)r * (SEQ/2) + kt * 32 + seg * 4;
        else               src = vlp + (size_t)r * (SEQ/2) + kt * 32 + seg * 4;
        uint32_t dst = (uint32_t)__cvta_generic_to_shared(
            &smu[base + arr * TSTRIDE + r * PP + seg * 4]);
        cp16(dst, src);
    }
    if (tid < 16)
        cp16((uint32_t)__cvta_generic_to_shared(&smu[base + 9216 + tid * 4]),
             mp + kt * 64 + tid * 4);
    CP_COMMIT();
}

__global__ __launch_bounds__(128, 2) void attn_kernel(
    const float* __restrict__ mask,   // [B,1,1,S]
    const float* __restrict__ rel,    // [B,NH,S,S]
    float* __restrict__ out)          // [B,S,H]
{
    extern __shared__ uint32_t smu[];   // 2 * 9280 u32 = 74240 B

    const int qt = blockIdx.x;        // 0..15
    const int bh = blockIdx.y;        // 0..63
    const int b = bh >> 3;
    const int h = bh & 7;

    const uint32_t* qhp = g_qh + (size_t)bh * SEQ * 32;
    const uint32_t* qlp = g_ql + (size_t)bh * SEQ * 32;
    const uint32_t* khp = g_kh + (size_t)bh * SEQ * 32;
    const uint32_t* klp = g_kl + (size_t)bh * SEQ * 32;
    const uint32_t* vhp = g_vth + (size_t)bh * HDIM * (SEQ/2);
    const uint32_t* vlp = g_vtl + (size_t)bh * HDIM * (SEQ/2);
    const float* relp = rel + (size_t)bh * SEQ * SEQ;
    const float* mp = mask + (size_t)b * SEQ;

    const int tid = threadIdx.x;
    const int lane = tid & 31;
    const int w = tid >> 5;
    const int g = lane >> 2;
    const int tig = lane & 3;
    const unsigned FULL = 0xffffffffu;

    const uint32_t smaddr = (uint32_t)__cvta_generic_to_shared(smu);
    const int q8 = lane >> 3;
    const int rl = lane & 7;
    const uint32_t laneB = (((q8 >> 1) * 8 + rl) * PP + (q8 & 1) * 4) * 4;

    attn_issue(smu, 0, 0, tid, khp, klp, vhp, vlp, mp);  // prefetch tile 0

    // Q A-fragments straight from global (latency overlaps the prefetch)
    const int rA = qt * 64 + w * 16 + g;
    uint32_t qh[4][4], ql[4][4];
#pragma unroll
    for (int kc = 0; kc < 4; kc++) {
        size_t r0 = (size_t)rA * 32 + kc * 8 + tig;
        size_t r1 = (size_t)(rA + 8) * 32 + kc * 8 + tig;
        qh[kc][0] = qhp[r0]; qh[kc][1] = qhp[r1];
        qh[kc][2] = qhp[r0 + 4]; qh[kc][3] = qhp[r1 + 4];
        ql[kc][0] = qlp[r0]; ql[kc][1] = qlp[r1];
        ql[kc][2] = qlp[r0 + 4]; ql[kc][3] = qlp[r1 + 4];
    }

    float o[8][4];
#pragma unroll
    for (int nt = 0; nt < 8; nt++)
#pragma unroll
        for (int j = 0; j < 4; j++) o[nt][j] = 0.f;
    float m0 = -1e30f, m1 = -1e30f, l0r = 0.f, l1r = 0.f;

    for (int kt = 0; kt < 16; kt++) {
        int p = kt & 1;
        if (kt < 15) {
            attn_issue(smu, kt + 1, 1 - p, tid, khp, klp, vhp, vlp, mp);
            CP_WAIT(1);
        } else CP_WAIT(0);
        __syncthreads();

        const uint32_t Khi_a = smaddr + p * ASTG * 4;
        const uint32_t Klo_a = Khi_a + TSTRIDE * 4;
        const uint32_t Vhi_a = Khi_a + 2 * TSTRIDE * 4;
        const uint32_t Vlo_a = Khi_a + 3 * TSTRIDE * 4;
        const float* Msf = (const float*)(smu + p * ASTG + 9216);

        // Prefetch rel-bias into registers: DRAM latency overlaps S-MMA loop
        const float* rrA = relp + (size_t)rA * SEQ + kt * 64;
        const float* rrB = rrA + (size_t)8 * SEQ;
        float2 bA[8], bB[8];
#pragma unroll
        for (int nt = 0; nt < 8; nt++) {
            int c = nt * 8 + 2 * tig;
            bA[nt] = *(const float2*)&rrA[c];
            bB[nt] = *(const float2*)&rrB[c];
        }

        // S = Q K^T (scale folded into K)
        float s[8][4];
#pragma unroll
        for (int nt = 0; nt < 8; nt++)
#pragma unroll
            for (int j = 0; j < 4; j++) s[nt][j] = 0.f;

#pragma unroll
        for (int kc = 0; kc < 4; kc++) {
            // All K fragment loads first
            uint32_t kh[4][4], kl[4][4];
#pragma unroll
            for (int ntp = 0; ntp < 4; ntp++) {
                uint32_t boff = laneB + (uint32_t)(ntp * 16 * PP * 4) + kc * 32;
                ldsm_x4(kh[ntp][0], kh[ntp][1], kh[ntp][2], kh[ntp][3], Khi_a + boff);
                ldsm_x4(kl[ntp][0], kl[ntp][1], kl[ntp][2], kl[ntp][3], Klo_a + boff);
            }
            // Round-robin over 8 accumulators: hh, then hl, then lh
#pragma unroll
            for (int ntp = 0; ntp < 4; ntp++) {
                mma16816(s[2 * ntp],     qh[kc][0], qh[kc][1], qh[kc][2], qh[kc][3], kh[ntp][0], kh[ntp][1]);
                mma16816(s[2 * ntp + 1], qh[kc][0], qh[kc][1], qh[kc][2], qh[kc][3], kh[ntp][2], kh[ntp][3]);
            }
#pragma unroll
            for (int ntp = 0; ntp < 4; ntp++) {
                mma16816(s[2 * ntp],     qh[kc][0], qh[kc][1], qh[kc][2], qh[kc][3], kl[ntp][0], kl[ntp][1]);
                mma16816(s[2 * ntp + 1], qh[kc][0], qh[kc][1], qh[kc][2], qh[kc][3], kl[ntp][2], kl[ntp][3]);
            }
#pragma unroll
            for (int ntp = 0; ntp < 4; ntp++) {
                mma16816(s[2 * ntp],     ql[kc][0], ql[kc][1], ql[kc][2], ql[kc][3], kh[ntp][0], kh[ntp][1]);
                mma16816(s[2 * ntp + 1], ql[kc][0], ql[kc][1], ql[kc][2], ql[kc][3], kh[ntp][2], kh[ntp][3]);
            }
        }

        // + rel bias + mask
#pragma unroll
        for (int nt = 0; nt < 8; nt++) {
            int c = nt * 8 + 2 * tig;
            float mm0 = Msf[c], mm1 = Msf[c + 1];
            s[nt][0] += bA[nt].x + mm0;
            s[nt][1] += bA[nt].y + mm1;
            s[nt][2] += bB[nt].x + mm0;
            s[nt][3] += bB[nt].y + mm1;
        }

        // Online softmax (row halves live in quads; shfl width 4)
        float mx0 = -1e30f, mx1 = -1e30f;
#pragma unroll
        for (int nt = 0; nt < 8; nt++) {
            mx0 = fmaxf(mx0, fmaxf(s[nt][0], s[nt][1]));
            mx1 = fmaxf(mx1, fmaxf(s[nt][2], s[nt][3]));
        }
        mx0 = fmaxf(mx0, __shfl_xor_sync(FULL, mx0, 1, 4));
        mx0 = fmaxf(mx0, __shfl_xor_sync(FULL, mx0, 2, 4));
        mx1 = fmaxf(mx1, __shfl_xor_sync(FULL, mx1, 1, 4));
        mx1 = fmaxf(mx1, __shfl_xor_sync(FULL, mx1, 2, 4));
        float mn0 = fmaxf(m0, mx0), mn1 = fmaxf(m1, mx1);
        float cor0 = __expf(m0 - mn0), cor1 = __expf(m1 - mn1);

        float sum0 = 0.f, sum1 = 0.f;
#pragma unroll
        for (int nt = 0; nt < 8; nt++) {
            s[nt][0] = __expf(s[nt][0] - mn0); sum0 += s[nt][0];
            s[nt][1] = __expf(s[nt][1] - mn0); sum0 += s[nt][1];
            s[nt][2] = __expf(s[nt][2] - mn1); sum1 += s[nt][2];
            s[nt][3] = __expf(s[nt][3] - mn1); sum1 += s[nt][3];
        }
        sum0 += __shfl_xor_sync(FULL, sum0, 1, 4);
        sum0 += __shfl_xor_sync(FULL, sum0, 2, 4);
        sum1 += __shfl_xor_sync(FULL, sum1, 1, 4);
        sum1 += __shfl_xor_sync(FULL, sum1, 2, 4);
        l0r = l0r * cor0 + sum0;  m0 = mn0;
        l1r = l1r * cor1 + sum1;  m1 = mn1;

#pragma unroll
        for (int nt = 0; nt < 8; nt++) {
            o[nt][0] *= cor0; o[nt][1] *= cor0;
            o[nt][2] *= cor1; o[nt][3] *= cor1;
        }

        // O += P @ V.  P C-frag == A-frag layout: pure packs, no shuffles.
#pragma unroll
        for (int kk = 0; kk < 4; kk++) {
            uint32_t ah[4], al[4];
            split2(s[2 * kk][0],     s[2 * kk][1],     ah[0], al[0]);
            split2(s[2 * kk][2],     s[2 * kk][3],     ah[1], al[1]);
            split2(s[2 * kk + 1][0], s[2 * kk + 1][1], ah[2], al[2]);
            split2(s[2 * kk + 1][2], s[2 * kk + 1][3], ah[3], al[3]);
            // All V fragment loads first
            uint32_t vh[4][4], vl[4][4];
#pragma unroll
            for (int ntp = 0; ntp < 4; ntp++) {
                uint32_t boff = laneB + (uint32_t)(ntp * 16 * PP * 4) + kk * 32;
                ldsm_x4(vh[ntp][0], vh[ntp][1], vh[ntp][2], vh[ntp][3], Vhi_a + boff);
                ldsm_x4(vl[ntp][0], vl[ntp][1], vl[ntp][2], vl[ntp][3], Vlo_a + boff);
            }
            // Round-robin over 8 accumulators: hh, then hl, then lh
#pragma unroll
            for (int ntp = 0; ntp < 4; ntp++) {
                mma16816(o[2 * ntp],     ah[0], ah[1], ah[2], ah[3], vh[ntp][0], vh[ntp][1]);
                mma16816(o[2 * ntp + 1], ah[0], ah[1], ah[2], ah[3], vh[ntp][2], vh[ntp][3]);
            }
#pragma unroll
            for (int ntp = 0; ntp < 4; ntp++) {
                mma16816(o[2 * ntp],     ah[0], ah[1], ah[2], ah[3], vl[ntp][0], vl[ntp][1]);
                mma16816(o[2 * ntp + 1], ah[0], ah[1], ah[2], ah[3], vl[ntp][2], vl[ntp][3]);
            }
#pragma unroll
            for (int ntp = 0; ntp < 4; ntp++) {
                mma16816(o[2 * ntp],     al[0], al[1], al[2], al[3], vh[ntp][0], vh[ntp][1]);
                mma16816(o[2 * ntp + 1], al[0], al[1], al[2], al[3], vh[ntp][2], vh[ntp][3]);
            }
        }
        __syncthreads();
    }

    // Epilogue: normalize, write [B, S, H]
    float il0 = 1.f / l0r, il1 = 1.f / l1r;
    size_t base0 = ((size_t)b * SEQ + rA) * HID + h * HDIM;
    size_t base1 = base0 + (size_t)8 * HID;
#pragma unroll
    for (int nt = 0; nt < 8; nt++) {
        int d = nt * 8 + 2 * tig;
        *(float2*)&out[base0 + d] = make_float2(o[nt][0] * il0, o[nt][1] * il0);
        *(float2*)&out[base1 + d] = make_float2(o[nt][2] * il1, o[nt][3] * il1);
    }
}

// ---------------------------------------------------------------------------
extern "C" void kernel_launch(void* const* d_in, const int* in_sizes, int n_in,
                              void* d_out, int out_size)
{
    const float* hs   = (const float*)d_in[0];
    const float* mask = (const float*)d_in[1];
    const float* rel  = (const float*)d_in[2];
    const float* Wq   = (const float*)d_in[3];
    const float* bq   = (const float*)d_in[4];
    const float* Wk   = (const float*)d_in[5];
    const float* bk   = (const float*)d_in[6];
    const float* Wv   = (const float*)d_in[7];
    const float* bv   = (const float*)d_in[8];
    float* out = (float*)d_out;

    // Unconditional every call (no static guards — harness rule).
    cudaFuncSetAttribute(qkv_kernel,
        cudaFuncAttributeMaxDynamicSharedMemorySize, 8 * TSTRIDE * 4);
    cudaFuncSetAttribute(attn_kernel,
        cudaFuncAttributeMaxDynamicSharedMemorySize, 2 * ASTG * 4);

    split_kernel<<<XROWS, 128>>>(hs, Wq, Wk, Wv);

    dim3 g1(ROWS / 64, 24);
    qkv_kernel<<<g1, 128, 8 * TSTRIDE * 4>>>(bq, bk, bv);

    dim3 gv(SEQ / 64, BH);
    vtrans_kernel<<<gv, 256>>>();

    dim3 g2(SEQ / 64, BH);
    attn_kernel<<<g2, 128, 2 * ASTG * 4>>>(mask, rel, out);
}

// round 16
// speedup vs baseline: 1.2418x; 1.2418x over previous
#include <cuda_runtime.h>
#include <cuda_bf16.h>
#include <cuda_fp16.h>
#include <cstdint>

// Problem constants
#define Bsz 8
#define SEQ 1024
#define HID 512
#define NHEAD 8
#define HDIM 64
#define BH (Bsz*NHEAD)          // 64
#define ROWS (Bsz*SEQ)          // 8192
#define XROWS (ROWS + 3*HID)    // 9728 : X rows then Wq,Wk,Wv rows

// ---------------------------------------------------------------------------
// Global scratch (pre-split operands, all half2-packed in uint32)
// ---------------------------------------------------------------------------
__device__ uint32_t g_xh[XROWS * (HID/2)];      // X/W hi  [row][256]
__device__ uint32_t g_xl[XROWS * (HID/2)];      // X/W lo
__device__ uint32_t g_qh[BH * SEQ * (HDIM/2)];  // Q hi    [bh][s][32]
__device__ uint32_t g_kh[BH * SEQ * (HDIM/2)];  // K hi (pre-scaled by 1/8)
__device__ uint32_t g_kl[BH * SEQ * (HDIM/2)];
__device__ float    g_v [BH * SEQ * HDIM];      // V fp32 [bh][s][d]
__device__ uint32_t g_vth[BH * HDIM * (SEQ/2)]; // V^T hi [bh][d][s-pair]

// ---------------------------------------------------------------------------
// MMA + helpers
// ---------------------------------------------------------------------------
__device__ __forceinline__ void mma16816(float c[4],
    uint32_t a0, uint32_t a1, uint32_t a2, uint32_t a3,
    uint32_t b0, uint32_t b1)
{
    asm volatile(
        "mma.sync.aligned.m16n8k16.row.col.f32.f16.f16.f32 "
        "{%0,%1,%2,%3}, {%4,%5,%6,%7}, {%8,%9}, {%0,%1,%2,%3};\n"
        : "+f"(c[0]), "+f"(c[1]), "+f"(c[2]), "+f"(c[3])
        : "r"(a0), "r"(a1), "r"(a2), "r"(a3), "r"(b0), "r"(b1));
}

// ldmatrix x4: 4 8x8 b16 matrices; lane L supplies row addr for matrix L/8.
__device__ __forceinline__ void ldsm_x4(uint32_t& r0, uint32_t& r1,
                                        uint32_t& r2, uint32_t& r3,
                                        uint32_t addr)
{
    asm volatile(
        "ldmatrix.sync.aligned.m8n8.x4.shared.b16 {%0,%1,%2,%3}, [%4];\n"
        : "=r"(r0), "=r"(r1), "=r"(r2), "=r"(r3) : "r"(addr));
}

__device__ __forceinline__ uint32_t pack_half2(__half a, __half b) {
    return (uint32_t)__half_as_ushort(a) | ((uint32_t)__half_as_ushort(b) << 16);
}
__device__ __forceinline__ void split2(float x, float y, uint32_t& hi, uint32_t& lo) {
    __half hx = __float2half_rn(x), hy = __float2half_rn(y);
    __half lx = __float2half_rn(x - __half2float(hx));
    __half ly = __float2half_rn(y - __half2float(hy));
    hi = pack_half2(hx, hy);
    lo = pack_half2(lx, ly);
}

__device__ __forceinline__ void cp16(uint32_t dst_smem, const void* src) {
    asm volatile("cp.async.cg.shared.global [%0], [%1], 16;\n"
                 :: "r"(dst_smem), "l"(src));
}
#define CP_COMMIT() asm volatile("cp.async.commit_group;\n")
#define CP_WAIT(N)  asm volatile("cp.async.wait_group %0;\n" :: "n"(N))

// smem pitch in uint32 (32 data + 4 pad). LDSM: row r -> bank 4r mod 32,
// 8 rows x 16B cover all 32 banks exactly once -> conflict-free.
#define PP 36
#define TSTRIDE (64 * PP)       // 2304 u32 per tile

// ---------------------------------------------------------------------------
// 1) Split X (8192 rows) and W (1536 rows: Wq,Wk,Wv) into hi/lo half2.
// ---------------------------------------------------------------------------
__global__ __launch_bounds__(128) void split_kernel(
    const float* __restrict__ X,
    const float* __restrict__ Wq, const float* __restrict__ Wk,
    const float* __restrict__ Wv)
{
    const int r = blockIdx.x;
    const int tid = threadIdx.x;
    const float* src;
    if (r < ROWS) src = X + (size_t)r * HID;
    else {
        int wr = r - ROWS;
        const float* W = (wr >> 9) == 0 ? Wq : (wr >> 9) == 1 ? Wk : Wv;
        src = W + (size_t)(wr & 511) * HID;
    }
    float4 v4 = *(const float4*)&src[tid * 4];
    uint32_t h0, l0, h1, l1;
    split2(v4.x, v4.y, h0, l0);
    split2(v4.z, v4.w, h1, l1);
    size_t o = (size_t)r * (HID/2) + tid * 2;
    g_xh[o] = h0; g_xh[o + 1] = h1;
    g_xl[o] = l0; g_xl[o + 1] = l1;
}

// ---------------------------------------------------------------------------
// 2) QKV GEMM on pre-split operands (3-term split, full accuracy).
//    cp.async 2-stage pipeline + ldmatrix. 64x64 tile, 128 threads.
// ---------------------------------------------------------------------------
__device__ __forceinline__ void qkv_issue(
    uint32_t* smu, int st, int sg, int tid, int row0, int wrow0)
{
    const int kb32 = st * 32;           // u32 col offset within 256-wide row
    const uint32_t base = sg * (4 * TSTRIDE);
#pragma unroll
    for (int u = 0; u < 16; u++) {
        int t = u * 128 + tid;
        int arr = t >> 9;
        int rem = t & 511;
        int r = rem >> 3, seg = rem & 7;
        const uint32_t* src;
        if (arr == 0)      src = g_xh + (size_t)(row0 + r) * 256 + kb32 + seg * 4;
        else if (arr == 1) src = g_xl + (size_t)(row0 + r) * 256 + kb32 + seg * 4;
        else if (arr == 2) src = g_xh + (size_t)(wrow0 + r) * 256 + kb32 + seg * 4;
        else               src = g_xl + (size_t)(wrow0 + r) * 256 + kb32 + seg * 4;
        uint32_t dst = (uint32_t)__cvta_generic_to_shared(
            &smu[base + arr * TSTRIDE + r * PP + seg * 4]);
        cp16(dst, src);
    }
    CP_COMMIT();
}

__global__ __launch_bounds__(128, 2) void qkv_kernel(
    const float* __restrict__ bq, const float* __restrict__ bk,
    const float* __restrict__ bv)
{
    extern __shared__ uint32_t smu[];   // 2 stages x 4 tiles x 2304 = 73728 B
    const int ib = blockIdx.x;          // 128 row tiles
    const int jb = blockIdx.y;          // 24 col tiles
    const int jsel = jb >> 3;           // 0=Q 1=K 2=V
    const int h = jb & 7;

    const float* bias = (jsel == 0) ? bq : (jsel == 1) ? bk : bv;

    const int tid = threadIdx.x;
    const int lane = tid & 31;
    const int w = tid >> 5;
    const int g = lane >> 2;
    const int tig = lane & 3;
    const int row0 = ib * 64;
    const int wrow0 = ROWS + jsel * HID + h * 64;

    const uint32_t smaddr = (uint32_t)__cvta_generic_to_shared(smu);
    const int q8 = lane >> 3;          // 0..3: ldmatrix matrix index
    const int rl = lane & 7;           // row within 8x8 matrix
    const uint32_t laneA = ((w * 16 + (q8 & 1) * 8 + rl) * PP + (q8 >> 1) * 4) * 4;
    const uint32_t laneB = (((q8 >> 1) * 8 + rl) * PP + (q8 & 1) * 4) * 4;

    float acc[8][4];
#pragma unroll
    for (int nt = 0; nt < 8; nt++)
#pragma unroll
        for (int j = 0; j < 4; j++) acc[nt][j] = 0.f;

    qkv_issue(smu, 0, 0, tid, row0, wrow0);

    for (int st = 0; st < 8; st++) {
        int p = st & 1;
        if (st < 7) { qkv_issue(smu, st + 1, 1 - p, tid, row0, wrow0); CP_WAIT(1); }
        else CP_WAIT(0);
        __syncthreads();

        const uint32_t Xhi_a = smaddr + p * (4 * TSTRIDE) * 4;
        const uint32_t Xlo_a = Xhi_a + TSTRIDE * 4;
        const uint32_t Whi_a = Xhi_a + 2 * TSTRIDE * 4;
        const uint32_t Wlo_a = Xhi_a + 3 * TSTRIDE * 4;

#pragma unroll
        for (int kc = 0; kc < 4; kc++) {
            uint32_t ah0, ah1, ah2, ah3, al0, al1, al2, al3;
            ldsm_x4(ah0, ah1, ah2, ah3, Xhi_a + laneA + kc * 32);
            ldsm_x4(al0, al1, al2, al3, Xlo_a + laneA + kc * 32);
#pragma unroll
            for (int ntp = 0; ntp < 4; ntp++) {
                uint32_t boff = laneB + (uint32_t)(ntp * 16 * PP * 4) + kc * 32;
                uint32_t bh0, bh1, bh2, bh3, bl0, bl1, bl2, bl3;
                ldsm_x4(bh0, bh1, bh2, bh3, Whi_a + boff);
                ldsm_x4(bl0, bl1, bl2, bl3, Wlo_a + boff);
                mma16816(acc[2 * ntp],     ah0, ah1, ah2, ah3, bh0, bh1);
                mma16816(acc[2 * ntp],     ah0, ah1, ah2, ah3, bl0, bl1);
                mma16816(acc[2 * ntp],     al0, al1, al2, al3, bh0, bh1);
                mma16816(acc[2 * ntp + 1], ah0, ah1, ah2, ah3, bh2, bh3);
                mma16816(acc[2 * ntp + 1], ah0, ah1, ah2, ah3, bl2, bl3);
                mma16816(acc[2 * ntp + 1], al0, al1, al2, al3, bh2, bh3);
            }
        }
        __syncthreads();
    }

    // Epilogue
    const int grow0 = row0 + w * 16 + g;
    const int grow1 = grow0 + 8;
    const int b0i = grow0 >> 10, s0 = grow0 & 1023;
    const int b1i = grow1 >> 10, s1 = grow1 & 1023;
    const int bh0 = b0i * NHEAD + h, bh1 = b1i * NHEAD + h;

    if (jsel == 2) {
        size_t base0 = ((size_t)bh0 * SEQ + s0) * HDIM;
        size_t base1 = ((size_t)bh1 * SEQ + s1) * HDIM;
#pragma unroll
        for (int nt = 0; nt < 8; nt++) {
            int d = nt * 8 + 2 * tig;
            float bv0 = bias[h * 64 + d], bv1 = bias[h * 64 + d + 1];
            *(float2*)&g_v[base0 + d] = make_float2(acc[nt][0] + bv0, acc[nt][1] + bv1);
            *(float2*)&g_v[base1 + d] = make_float2(acc[nt][2] + bv0, acc[nt][3] + bv1);
        }
    } else if (jsel == 0) {
        // Q: only hi half is consumed downstream
        size_t base0 = ((size_t)bh0 * SEQ + s0) * 32;
        size_t base1 = ((size_t)bh1 * SEQ + s1) * 32;
#pragma unroll
        for (int nt = 0; nt < 8; nt++) {
            int d = nt * 8 + 2 * tig;
            int uc = nt * 4 + tig;
            float bv0 = bias[h * 64 + d], bv1 = bias[h * 64 + d + 1];
            uint32_t hi, lo;
            split2(acc[nt][0] + bv0, acc[nt][1] + bv1, hi, lo);
            g_qh[base0 + uc] = hi;
            split2(acc[nt][2] + bv0, acc[nt][3] + bv1, hi, lo);
            g_qh[base1 + uc] = hi;
        }
    } else {
        // K: hi+lo, pre-scaled by 1/8 (exact)
        size_t base0 = ((size_t)bh0 * SEQ + s0) * 32;
        size_t base1 = ((size_t)bh1 * SEQ + s1) * 32;
#pragma unroll
        for (int nt = 0; nt < 8; nt++) {
            int d = nt * 8 + 2 * tig;
            int uc = nt * 4 + tig;
            float bv0 = bias[h * 64 + d], bv1 = bias[h * 64 + d + 1];
            uint32_t hi, lo;
            split2((acc[nt][0] + bv0) * 0.125f, (acc[nt][1] + bv1) * 0.125f, hi, lo);
            g_kh[base0 + uc] = hi; g_kl[base0 + uc] = lo;
            split2((acc[nt][2] + bv0) * 0.125f, (acc[nt][3] + bv1) * 0.125f, hi, lo);
            g_kh[base1 + uc] = hi; g_kl[base1 + uc] = lo;
        }
    }
}

// ---------------------------------------------------------------------------
// 3) Transpose + split V:  g_v [bh][s][d] -> g_vth [bh][d][s-pair] (hi only)
// ---------------------------------------------------------------------------
__global__ __launch_bounds__(256) void vtrans_kernel()
{
    __shared__ float Vs[64][65];
    const int stile = blockIdx.x;       // 0..15
    const int bh = blockIdx.y;          // 0..63
    const int tid = threadIdx.x;

#pragma unroll
    for (int u = 0; u < 4; u++) {
        int e = u * 256 + tid;
        int r = e >> 4, c4 = (e & 15) * 4;
        float4 v4 = *(const float4*)&g_v[((size_t)bh * SEQ + stile * 64 + r) * HDIM + c4];
        Vs[r][c4 + 0] = v4.x; Vs[r][c4 + 1] = v4.y;
        Vs[r][c4 + 2] = v4.z; Vs[r][c4 + 3] = v4.w;
    }
    __syncthreads();

    const int d = tid >> 2;
    const int q = tid & 3;
    size_t obase = ((size_t)bh * HDIM + d) * (SEQ/2) + stile * 32;
#pragma unroll
    for (int i = 0; i < 8; i++) {
        int sp = q * 8 + i;
        g_vth[obase + sp] = pack_half2(__float2half_rn(Vs[2 * sp][d]),
                                       __float2half_rn(Vs[2 * sp + 1][d]));
    }
}

// ---------------------------------------------------------------------------
// 4) Flash attention: 64-row q-tile, 128 threads / 4 warps, 2-stage cp.async,
//    ldmatrix loads. S = Qhi*(Khi+Klo); PV = (Phi+Plo)*Vhi.
//    Stage layout (u32): Khi@0 Klo@2304 Vhi@4608 Ms@6912(+64)
//    3 blocks/SM (170-reg cap) for latency hiding.
// ---------------------------------------------------------------------------
#define ASTG 6976

__device__ __forceinline__ void attn_issue(
    uint32_t* smu, int kt, int sg, int tid,
    const uint32_t* khp, const uint32_t* klp,
    const uint32_t* vhp, const float* mp)
{
    const uint32_t base = sg * ASTG;
#pragma unroll
    for (int u = 0; u < 12; u++) {
        int t = u * 128 + tid;
        int arr = t >> 9;               // 0=Khi 1=Klo 2=Vhi
        int rem = t & 511;
        int r = rem >> 3, seg = rem & 7;
        const uint32_t* src;
        if (arr == 0)      src = khp + (size_t)(kt * 64 + r) * 32 + seg * 4;
        else if (arr == 1) src = klp + (size_t)(kt * 64 + r) * 32 + seg * 4;
        else               src = vhp + (size_t)r * (SEQ/2) + kt * 32 + seg * 4;
        uint32_t dst = (uint32_t)__cvta_generic_to_shared(
            &smu[base + arr * TSTRIDE + r * PP + seg * 4]);
        cp16(dst, src);
    }
    if (tid < 16)
        cp16((uint32_t)__cvta_generic_to_shared(&smu[base + 6912 + tid * 4]),
             mp + kt * 64 + tid * 4);
    CP_COMMIT();
}

__global__ __launch_bounds__(128, 3) void attn_kernel(
    const float* __restrict__ mask,   // [B,1,1,S]
    const float* __restrict__ rel,    // [B,NH,S,S]
    float* __restrict__ out)          // [B,S,H]
{
    extern __shared__ uint32_t smu[];   // 2 * 6976 u32 = 55808 B

    const int qt = blockIdx.x;        // 0..15
    const int bh = blockIdx.y;        // 0..63
    const int b = bh >> 3;
    const int h = bh & 7;

    const uint32_t* qhp = g_qh + (size_t)bh * SEQ * 32;
    const uint32_t* khp = g_kh + (size_t)bh * SEQ * 32;
    const uint32_t* klp = g_kl + (size_t)bh * SEQ * 32;
    const uint32_t* vhp = g_vth + (size_t)bh * HDIM * (SEQ/2);
    const float* relp = rel + (size_t)bh * SEQ * SEQ;
    const float* mp = mask + (size_t)b * SEQ;

    const int tid = threadIdx.x;
    const int lane = tid & 31;
    const int w = tid >> 5;
    const int g = lane >> 2;
    const int tig = lane & 3;
    const unsigned FULL = 0xffffffffu;

    const uint32_t smaddr = (uint32_t)__cvta_generic_to_shared(smu);
    const int q8 = lane >> 3;
    const int rl = lane & 7;
    const uint32_t laneB = (((q8 >> 1) * 8 + rl) * PP + (q8 & 1) * 4) * 4;

    attn_issue(smu, 0, 0, tid, khp, klp, vhp, mp);  // prefetch tile 0

    // Q hi A-fragments straight from global (latency overlaps the prefetch)
    const int rA = qt * 64 + w * 16 + g;
    uint32_t qh[4][4];
#pragma unroll
    for (int kc = 0; kc < 4; kc++) {
        size_t r0 = (size_t)rA * 32 + kc * 8 + tig;
        size_t r1 = (size_t)(rA + 8) * 32 + kc * 8 + tig;
        qh[kc][0] = qhp[r0]; qh[kc][1] = qhp[r1];
        qh[kc][2] = qhp[r0 + 4]; qh[kc][3] = qhp[r1 + 4];
    }

    float o[8][4];
#pragma unroll
    for (int nt = 0; nt < 8; nt++)
#pragma unroll
        for (int j = 0; j < 4; j++) o[nt][j] = 0.f;
    float m0 = -1e30f, m1 = -1e30f, l0r = 0.f, l1r = 0.f;

    for (int kt = 0; kt < 16; kt++) {
        int p = kt & 1;
        if (kt < 15) {
            attn_issue(smu, kt + 1, 1 - p, tid, khp, klp, vhp, mp);
            CP_WAIT(1);
        } else CP_WAIT(0);
        __syncthreads();

        const uint32_t Khi_a = smaddr + p * ASTG * 4;
        const uint32_t Klo_a = Khi_a + TSTRIDE * 4;
        const uint32_t Vhi_a = Khi_a + 2 * TSTRIDE * 4;
        const float* Msf = (const float*)(smu + p * ASTG + 6912);

        // Prefetch rel-bias into registers: DRAM latency overlaps S-MMA loop
        const float* rrA = relp + (size_t)rA * SEQ + kt * 64;
        const float* rrB = rrA + (size_t)8 * SEQ;
        float2 bA[8], bB[8];
#pragma unroll
        for (int nt = 0; nt < 8; nt++) {
            int c = nt * 8 + 2 * tig;
            bA[nt] = *(const float2*)&rrA[c];
            bB[nt] = *(const float2*)&rrB[c];
        }

        // S = Qhi (Khi + Klo)   (scale folded into K; Qlo term dropped:
        // |err| ~5e-5 absolute on scores, negligible through exp)
        float s[8][4];
#pragma unroll
        for (int nt = 0; nt < 8; nt++)
#pragma unroll
            for (int j = 0; j < 4; j++) s[nt][j] = 0.f;

#pragma unroll
        for (int kc = 0; kc < 4; kc++) {
#pragma unroll
            for (int ntp = 0; ntp < 4; ntp++) {
                uint32_t boff = laneB + (uint32_t)(ntp * 16 * PP * 4) + kc * 32;
                uint32_t kh0, kh1, kh2, kh3, kl0, kl1, kl2, kl3;
                ldsm_x4(kh0, kh1, kh2, kh3, Khi_a + boff);
                ldsm_x4(kl0, kl1, kl2, kl3, Klo_a + boff);
                mma16816(s[2 * ntp],     qh[kc][0], qh[kc][1], qh[kc][2], qh[kc][3], kh0, kh1);
                mma16816(s[2 * ntp],     qh[kc][0], qh[kc][1], qh[kc][2], qh[kc][3], kl0, kl1);
                mma16816(s[2 * ntp + 1], qh[kc][0], qh[kc][1], qh[kc][2], qh[kc][3], kh2, kh3);
                mma16816(s[2 * ntp + 1], qh[kc][0], qh[kc][1], qh[kc][2], qh[kc][3], kl2, kl3);
            }
        }

        // + rel bias + mask
#pragma unroll
        for (int nt = 0; nt < 8; nt++) {
            int c = nt * 8 + 2 * tig;
            float mm0 = Msf[c], mm1 = Msf[c + 1];
            s[nt][0] += bA[nt].x + mm0;
            s[nt][1] += bA[nt].y + mm1;
            s[nt][2] += bB[nt].x + mm0;
            s[nt][3] += bB[nt].y + mm1;
        }

        // Online softmax (row halves live in quads; shfl width 4)
        float mx0 = -1e30f, mx1 = -1e30f;
#pragma unroll
        for (int nt = 0; nt < 8; nt++) {
            mx0 = fmaxf(mx0, fmaxf(s[nt][0], s[nt][1]));
            mx1 = fmaxf(mx1, fmaxf(s[nt][2], s[nt][3]));
        }
        mx0 = fmaxf(mx0, __shfl_xor_sync(FULL, mx0, 1, 4));
        mx0 = fmaxf(mx0, __shfl_xor_sync(FULL, mx0, 2, 4));
        mx1 = fmaxf(mx1, __shfl_xor_sync(FULL, mx1, 1, 4));
        mx1 = fmaxf(mx1, __shfl_xor_sync(FULL, mx1, 2, 4));
        float mn0 = fmaxf(m0, mx0), mn1 = fmaxf(m1, mx1);
        float cor0 = __expf(m0 - mn0), cor1 = __expf(m1 - mn1);

        float sum0 = 0.f, sum1 = 0.f;
#pragma unroll
        for (int nt = 0; nt < 8; nt++) {
            s[nt][0] = __expf(s[nt][0] - mn0); sum0 += s[nt][0];
            s[nt][1] = __expf(s[nt][1] - mn0); sum0 += s[nt][1];
            s[nt][2] = __expf(s[nt][2] - mn1); sum1 += s[nt][2];
            s[nt][3] = __expf(s[nt][3] - mn1); sum1 += s[nt][3];
        }
        sum0 += __shfl_xor_sync(FULL, sum0, 1, 4);
        sum0 += __shfl_xor_sync(FULL, sum0, 2, 4);
        sum1 += __shfl_xor_sync(FULL, sum1, 1, 4);
        sum1 += __shfl_xor_sync(FULL, sum1, 2, 4);
        l0r = l0r * cor0 + sum0;  m0 = mn0;
        l1r = l1r * cor1 + sum1;  m1 = mn1;

#pragma unroll
        for (int nt = 0; nt < 8; nt++) {
            o[nt][0] *= cor0; o[nt][1] *= cor0;
            o[nt][2] *= cor1; o[nt][3] *= cor1;
        }

        // O += P @ Vhi with P = Phi + Plo (22-bit): P*Vlo term dropped,
        // rel err ~2^-12. P C-frag == A-frag layout: pure packs, no shuffles.
#pragma unroll
        for (int kk = 0; kk < 4; kk++) {
            uint32_t ah[4], al[4];
            split2(s[2 * kk][0],     s[2 * kk][1],     ah[0], al[0]);
            split2(s[2 * kk][2],     s[2 * kk][3],     ah[1], al[1]);
            split2(s[2 * kk + 1][0], s[2 * kk + 1][1], ah[2], al[2]);
            split2(s[2 * kk + 1][2], s[2 * kk + 1][3], ah[3], al[3]);
#pragma unroll
            for (int ntp = 0; ntp < 4; ntp++) {
                uint32_t boff = laneB + (uint32_t)(ntp * 16 * PP * 4) + kk * 32;
                uint32_t vh0, vh1, vh2, vh3;
                ldsm_x4(vh0, vh1, vh2, vh3, Vhi_a + boff);
                mma16816(o[2 * ntp],     ah[0], ah[1], ah[2], ah[3], vh0, vh1);
                mma16816(o[2 * ntp],     al[0], al[1], al[2], al[3], vh0, vh1);
                mma16816(o[2 * ntp + 1], ah[0], ah[1], ah[2], ah[3], vh2, vh3);
                mma16816(o[2 * ntp + 1], al[0], al[1], al[2], al[3], vh2, vh3);
            }
        }
        __syncthreads();
    }

    // Epilogue: normalize, write [B, S, H]
    float il0 = 1.f / l0r, il1 = 1.f / l1r;
    size_t base0 = ((size_t)b * SEQ + rA) * HID + h * HDIM;
    size_t base1 = base0 + (size_t)8 * HID;
#pragma unroll
    for (int nt = 0; nt < 8; nt++) {
        int d = nt * 8 + 2 * tig;
        *(float2*)&out[base0 + d] = make_float2(o[nt][0] * il0, o[nt][1] * il0);
        *(float2*)&out[base1 + d] = make_float2(o[nt][2] * il1, o[nt][3] * il1);
    }
}

// ---------------------------------------------------------------------------
extern "C" void kernel_launch(void* const* d_in, const int* in_sizes, int n_in,
                              void* d_out, int out_size)
{
    const float* hs   = (const float*)d_in[0];
    const float* mask = (const float*)d_in[1];
    const float* rel  = (const float*)d_in[2];
    const float* Wq   = (const float*)d_in[3];
    const float* bq   = (const float*)d_in[4];
    const float* Wk   = (const float*)d_in[5];
    const float* bk   = (const float*)d_in[6];
    const float* Wv   = (const float*)d_in[7];
    const float* bv   = (const float*)d_in[8];
    float* out = (float*)d_out;

    // Unconditional every call (no static guards — harness rule).
    cudaFuncSetAttribute(qkv_kernel,
        cudaFuncAttributeMaxDynamicSharedMemorySize, 8 * TSTRIDE * 4);
    cudaFuncSetAttribute(attn_kernel,
        cudaFuncAttributeMaxDynamicSharedMemorySize, 2 * ASTG * 4);

    split_kernel<<<XROWS, 128>>>(hs, Wq, Wk, Wv);

    dim3 g1(ROWS / 64, 24);
    qkv_kernel<<<g1, 128, 8 * TSTRIDE * 4>>>(bq, bk, bv);

    dim3 gv(SEQ / 64, BH);
    vtrans_kernel<<<gv, 256>>>();

    dim3 g2(SEQ / 64, BH);
    attn_kernel<<<g2, 128, 2 * ASTG * 4>>>(mask, rel, out);
}